// round 6
// baseline (speedup 1.0000x reference)
#include <cuda_runtime.h>
#include <cstdint>

// out[dst[e]] += src_emb[src[e]] * att[e], D=64.
// R3-R5 established the L2 atomic-op floor (~39.5us) for the scatter-atomic
// formulation. This version removes ALL atomics from the main pass:
//   1) histogram dst            2) exclusive scan -> CSR offsets
//   3) scatter edges into dst-sorted (src, att) records
//   4) one warp per dst: pipelined gathers, register accumulate, single store.

static constexpr int D = 64;
static constexpr int E_MAX = 1 << 20;   // 1M edges  (actual: 800K)
static constexpr int N_MAX = 1 << 16;   // 64K nodes (actual: 50K)

__device__ int  g_counts[N_MAX];
__device__ int  g_fill[N_MAX];
__device__ int  g_offsets[N_MAX];
__device__ int2 g_sorted[E_MAX];        // (src_idx, att bits), grouped by dst

// ---------------------------------------------------------------- zero
__global__ void zero_kernel(int n) {
    int i = blockIdx.x * blockDim.x + threadIdx.x;
    if (i < n) { g_counts[i] = 0; g_fill[i] = 0; }
}

// ---------------------------------------------------------------- histogram
__global__ void hist_kernel(const int* __restrict__ dst, int E) {
    int e = blockIdx.x * blockDim.x + threadIdx.x;
    if (e < E) atomicAdd(&g_counts[dst[e]], 1);   // no return use -> RED
}

// ---------------------------------------------------------------- scan (1 block)
__global__ __launch_bounds__(1024)
void scan_kernel(int N) {
    __shared__ int sh[1024];
    const int tid = threadIdx.x;
    const int items = (N + 1023) >> 10;
    const int beg = tid * items;
    const int end = min(beg + items, N);

    int s = 0;
    for (int k = beg; k < end; k++) s += g_counts[k];
    sh[tid] = s;
    __syncthreads();

    // inclusive Hillis-Steele scan over 1024 partials
    for (int off = 1; off < 1024; off <<= 1) {
        int v = (tid >= off) ? sh[tid - off] : 0;
        __syncthreads();
        sh[tid] += v;
        __syncthreads();
    }

    int run = sh[tid] - s;   // exclusive base for this thread's segment
    for (int k = beg; k < end; k++) {
        g_offsets[k] = run;
        run += g_counts[k];
    }
}

// ---------------------------------------------------------------- scatter
__global__ void scatter_kernel(const int* __restrict__ src,
                               const int* __restrict__ dst,
                               const float* __restrict__ att, int E) {
    int e = blockIdx.x * blockDim.x + threadIdx.x;
    if (e >= E) return;
    const int d = dst[e];
    const int pos = g_offsets[d] + atomicAdd(&g_fill[d], 1);
    g_sorted[pos] = make_int2(src[e], __float_as_int(att[e]));
}

// ---------------------------------------------------------------- gather-sum
// One warp per dst row. Lane owns 2 consecutive floats (float2).
// Gathers pipelined 4-wide; accumulation in registers; one coalesced store.
__global__ __launch_bounds__(256)
void gather_sum_kernel(const float* __restrict__ src_emb,
                       float* __restrict__ out, int N) {
    const int w    = (blockIdx.x * 256 + threadIdx.x) >> 5;
    const int lane = threadIdx.x & 31;
    if (w >= N) return;

    const int start = g_offsets[w];
    const int cnt   = g_counts[w];
    const int2* rp  = g_sorted + start;

    float2 acc = make_float2(0.f, 0.f);

    int j = 0;
    for (; j + 4 <= cnt; j += 4) {
        const int2 r0 = __ldg(rp + j);
        const int2 r1 = __ldg(rp + j + 1);
        const int2 r2 = __ldg(rp + j + 2);
        const int2 r3 = __ldg(rp + j + 3);
        const float2 v0 = __ldcg(reinterpret_cast<const float2*>(src_emb + (unsigned)r0.x * D) + lane);
        const float2 v1 = __ldcg(reinterpret_cast<const float2*>(src_emb + (unsigned)r1.x * D) + lane);
        const float2 v2 = __ldcg(reinterpret_cast<const float2*>(src_emb + (unsigned)r2.x * D) + lane);
        const float2 v3 = __ldcg(reinterpret_cast<const float2*>(src_emb + (unsigned)r3.x * D) + lane);
        const float a0 = __int_as_float(r0.y), a1 = __int_as_float(r1.y);
        const float a2 = __int_as_float(r2.y), a3 = __int_as_float(r3.y);
        acc.x += v0.x * a0; acc.y += v0.y * a0;
        acc.x += v1.x * a1; acc.y += v1.y * a1;
        acc.x += v2.x * a2; acc.y += v2.y * a2;
        acc.x += v3.x * a3; acc.y += v3.y * a3;
    }
    for (; j < cnt; j++) {
        const int2 r = __ldg(rp + j);
        const float2 v = __ldcg(reinterpret_cast<const float2*>(src_emb + (unsigned)r.x * D) + lane);
        const float a = __int_as_float(r.y);
        acc.x += v.x * a; acc.y += v.y * a;
    }

    // Single coalesced 256B row store (also zeroes degree-0 rows).
    reinterpret_cast<float2*>(out + (size_t)w * D)[lane] = acc;
}

// ---------------------------------------------------------------- fallback (R3)
__global__ __launch_bounds__(256)
void atomic_fallback_kernel(const float* __restrict__ src_emb,
                            const float* __restrict__ e_att,
                            const int* __restrict__ src_idx,
                            const int* __restrict__ dst_idx,
                            float* __restrict__ out, int num_edges) {
    const long long tid  = (long long)blockIdx.x * blockDim.x + threadIdx.x;
    const long long edge = tid >> 4;
    const int lane = (int)(tid & 15);
    if (edge >= num_edges) return;
    const long long s = src_idx[edge];
    const long long d = dst_idx[edge];
    const float att = e_att[edge];
    const float4 v = *reinterpret_cast<const float4*>(src_emb + s * D + lane * 4);
    const float x = v.x * att, y = v.y * att, z = v.z * att, w = v.w * att;
    asm volatile("red.global.add.v4.f32 [%0], {%1, %2, %3, %4};"
                 :: "l"(out + d * D + lane * 4), "f"(x), "f"(y), "f"(z), "f"(w)
                 : "memory");
}

// ---------------------------------------------------------------- launch
extern "C" void kernel_launch(void* const* d_in, const int* in_sizes, int n_in,
                              void* d_out, int out_size)
{
    const float* src_emb = (const float*)d_in[0];   // [N_SRC, 64]
    const float* e_att   = (const float*)d_in[1];   // [E, 1]
    const int*   src_idx = (const int*)d_in[2];     // [E] int32
    const int*   dst_idx = (const int*)d_in[3];     // [E] int32
    float* out = (float*)d_out;                     // [N_DST, 64]

    const int E = in_sizes[2];
    const int N = out_size / D;

    if (E > E_MAX || N > N_MAX) {
        // Safety fallback: proven atomic path.
        cudaMemsetAsync(d_out, 0, (size_t)out_size * sizeof(float), 0);
        const long long total = (long long)E * 16;
        atomic_fallback_kernel<<<(int)((total + 255) / 256), 256>>>(
            src_emb, e_att, src_idx, dst_idx, out, E);
        return;
    }

    zero_kernel<<<(N + 255) / 256, 256>>>(N);
    hist_kernel<<<(E + 255) / 256, 256>>>(dst_idx, E);
    scan_kernel<<<1, 1024>>>(N);
    scatter_kernel<<<(E + 255) / 256, 256>>>(src_idx, dst_idx, e_att, E);
    gather_sum_kernel<<<(N * 32 + 255) / 256, 256>>>(src_emb, out, N);
}

// round 7
// speedup vs baseline: 2.1516x; 2.1516x over previous
#include <cuda_runtime.h>
#include <cstdint>

// out[dst[e]*64 + j] += src_emb[src[e]*64 + j] * att[e], D=64.
// R3-R5: scatter-atomic formulation pinned at the LTS reduce floor
// (~39.5us = 12.8M red.v4 ops @ 1 op/cyc/partition). This round replaces
// per-lane red.v4 (16B/op) with per-edge TMA bulk reductions (256B/op):
//   gather+scale into smem row  ->  cp.reduce.async.bulk .add.f32 (256B).

static constexpr int D = 64;
static constexpr int EPB = 64;          // edges per block
static constexpr int TASKS = 4;         // float4 lane-tasks per thread

__device__ __forceinline__ uint32_t smem_u32(const void* p) {
    uint32_t a;
    asm("{ .reg .u64 t; cvta.to.shared.u64 t, %1; cvt.u32.u64 %0, t; }"
        : "=r"(a) : "l"(p));
    return a;
}

__global__ __launch_bounds__(256)
void bulk_reduce_kernel(const float* __restrict__ src_emb,
                        const float* __restrict__ e_att,
                        const int* __restrict__ src_idx,
                        const int* __restrict__ dst_idx,
                        float* __restrict__ out,
                        int num_edges)
{
    __shared__ __align__(16) float s_msg[EPB * D];   // 16 KB message staging
    __shared__ int   s_src[EPB];
    __shared__ int   s_dst[EPB];
    __shared__ float s_att[EPB];

    const int t = threadIdx.x;
    const int base = blockIdx.x * EPB;

    // Stage edge metadata once per block. Invalid edges -> idx 0, att 0.
    if (t < EPB) {
        const int e = base + t;
        const bool valid = e < num_edges;
        s_src[t] = valid ? src_idx[e] : 0;
        s_dst[t] = valid ? dst_idx[e] : 0;
        s_att[t] = valid ? e_att[e]   : 0.0f;
    }
    __syncthreads();

    // Each thread owns 4 float4 lane-tasks. task = t + k*256;
    // edge slot = task>>4, lane = task&15 -> smem float offset = task*4
    // (edge-major rows: (task>>4)*64 + (task&15)*4 == task*4). Conflict-free.
    unsigned goff[TASKS];
    float att[TASKS];
#pragma unroll
    for (int k = 0; k < TASKS; k++) {
        const int task = t + k * 256;
        const int le   = task >> 4;
        const int lane = task & 15;
        goff[k] = (unsigned)s_src[le] * D + lane * 4;
        att[k]  = s_att[le];
    }

    // Batched random gathers (L2-only), then scale into smem rows.
    float4 v[TASKS];
#pragma unroll
    for (int k = 0; k < TASKS; k++) {
        v[k] = __ldcg(reinterpret_cast<const float4*>(src_emb + goff[k]));
    }
#pragma unroll
    for (int k = 0; k < TASKS; k++) {
        const int task = t + k * 256;
        float4 m;
        m.x = v[k].x * att[k];
        m.y = v[k].y * att[k];
        m.z = v[k].z * att[k];
        m.w = v[k].w * att[k];
        *reinterpret_cast<float4*>(s_msg + task * 4) = m;
    }
    __syncthreads();
    // Make generic-proxy smem writes visible to the async (TMA) proxy.
    asm volatile("fence.proxy.async.shared::cta;" ::: "memory");

    // One 256B bulk reduction per edge: out[dst*64 .. +64) += s_msg row.
    if (t < EPB && (base + t) < num_edges) {
        const uint32_t saddr = smem_u32(s_msg + t * D);
        float* g = out + (size_t)(unsigned)s_dst[t] * D;
        asm volatile(
            "cp.reduce.async.bulk.global.shared::cta.bulk_group.add.f32 "
            "[%0], [%1], %2;"
            :: "l"(g), "r"(saddr), "r"(256) : "memory");
    }
    asm volatile("cp.async.bulk.commit_group;" ::: "memory");
    asm volatile("cp.async.bulk.wait_group 0;" ::: "memory");
}

extern "C" void kernel_launch(void* const* d_in, const int* in_sizes, int n_in,
                              void* d_out, int out_size)
{
    const float* src_emb = (const float*)d_in[0];   // [N_SRC, 64]
    const float* e_att   = (const float*)d_in[1];   // [E, 1]
    const int*   src_idx = (const int*)d_in[2];     // [E] int32
    const int*   dst_idx = (const int*)d_in[3];     // [E] int32
    float* out = (float*)d_out;                     // [N_DST, 64]

    const int E = in_sizes[2];

    cudaMemsetAsync(d_out, 0, (size_t)out_size * sizeof(float), 0);

    const int grid = (E + EPB - 1) / EPB;
    bulk_reduce_kernel<<<grid, 256>>>(src_emb, e_att, src_idx, dst_idx, out, E);
}